// round 4
// baseline (speedup 1.0000x reference)
#include <cuda_runtime.h>
#include <cuda_pipeline.h>

// Problem constants (fixed by the dataset instance)
#define W_ 256
#define PLANE (256 * 256)
#define NTILES 2048          // 8 b x 64 ph x 4 pwg ; each tile = 16 patches (64c x 4r x 64w)
#define THREADS 512
#define TILE_FLOATS 16384    // 64 KB

__device__ __forceinline__ float sigm(float x) {
    return 1.0f / (1.0f + __expf(-x));
}

extern __shared__ float stage[];   // 2 x TILE_FLOATS (128 KB dynamic)

__global__ __launch_bounds__(THREADS, 1)
void ciam_persist_kernel(const float* __restrict__ x,
                         const float* __restrict__ fc_w,
                         const float* __restrict__ fc_b,
                         const float* __restrict__ c1w,
                         const float* __restrict__ c1b,
                         const float* __restrict__ c2w,
                         const float* __restrict__ c2b,
                         float* __restrict__ out)
{
    // ---- static shared work buffers (~43.8 KB) ----
    __shared__ float uni[4224];      // pm[4][1040] -> gsum/gmax -> p2s/p2m
    __shared__ float wS[64 * 68];    // fc_w rows, stride 68
    __shared__ float mxT[1024];      // channel maxes, k-major [k][p]
    __shared__ float msm[1024];      // channel attention m[c][p]
    __shared__ float g1s[256];
    __shared__ float fcbS[64];
    __shared__ float g2s[16];

    const int t  = threadIdx.x;
    const int p  = t & 15;           // patch
    const int r  = (t >> 4) & 3;     // row in patch
    const int cb = t >> 6;           // channel base group (c = cb + 8k)
    const int rp = t & 63;           // (r, patch)

    const float c1w0 = __ldg(c1w), c1w1 = __ldg(c1w + 1), c1b0 = __ldg(c1b);
    const float c2w0 = __ldg(c2w), c2w1 = __ldg(c2w + 1), c2b0 = __ldg(c2b);

    // ---- prefetch first tile into buffer 0 ----
    int tau = blockIdx.x;
    {
        const int pwg = tau & 3, ph = (tau >> 2) & 63, b = tau >> 8;
        const float* src = x + (size_t)b * 64 * PLANE + (ph * 4) * W_ + pwg * 64;
        #pragma unroll
        for (int i = 0; i < 8; i++) {
            const int j   = t + 512 * i;   // 0..4095 16B chunks
            const int c   = j >> 6;
            const int rr  = (j >> 4) & 3;
            const int w16 = j & 15;
            __pipeline_memcpy_async(stage + c * 256 + rr * 64 + w16 * 4,
                                    src + (size_t)c * PLANE + rr * W_ + w16 * 4, 16);
        }
    }
    __pipeline_commit();

    // ---- stage fc_w / fc_b (reused across all tiles) ----
    #pragma unroll
    for (int i = 0; i < 2; i++) {
        const int j  = t + 512 * i;        // float4 chunk 0..1023
        const int c  = j >> 4;
        const int k4 = j & 15;
        float4 wv = *(const float4*)(fc_w + c * 64 + k4 * 4);
        *(float4*)(wS + c * 68 + k4 * 4) = wv;
    }
    if (t < 64) fcbS[t] = fc_b[t];

    // ---- main tile loop with double-buffered prefetch ----
    int buf = 0;
    for (; tau < NTILES; tau += gridDim.x, buf ^= 1) {
        // issue prefetch of the next tile into the other buffer
        const int nxt = tau + gridDim.x;
        if (nxt < NTILES) {
            const int pwg = nxt & 3, ph = (nxt >> 2) & 63, b = nxt >> 8;
            const float* src = x + (size_t)b * 64 * PLANE + (ph * 4) * W_ + pwg * 64;
            float* dst = stage + (buf ^ 1) * TILE_FLOATS;
            #pragma unroll
            for (int i = 0; i < 8; i++) {
                const int j   = t + 512 * i;
                const int c   = j >> 6;
                const int rr  = (j >> 4) & 3;
                const int w16 = j & 15;
                __pipeline_memcpy_async(dst + c * 256 + rr * 64 + w16 * 4,
                                        src + (size_t)c * PLANE + rr * W_ + w16 * 4, 16);
            }
            __pipeline_commit();
            __pipeline_wait_prior(1);      // current tile's copy complete
        } else {
            __pipeline_wait_prior(0);
        }
        __syncthreads();                    // all threads' chunks visible

        // ---- load this thread's 32 values from staging ----
        const float4* b4 = (const float4*)(stage + buf * TILE_FLOATS);
        float4 v[8];
        #pragma unroll
        for (int k = 0; k < 8; k++) {
            const int c = cb + 8 * k;
            v[k] = b4[c * 64 + r * 16 + p];
        }

        // ---- per-(c,r,p) row max -> pm ----
        float* pm = uni;                    // [r][c*16+p], row stride 1040
        #pragma unroll
        for (int k = 0; k < 8; k++) {
            float4 a = v[k];
            pm[r * 1040 + (cb + 8 * k) * 16 + p] =
                fmaxf(fmaxf(a.x, a.y), fmaxf(a.z, a.w));
        }
        __syncthreads();

        // ---- reduce over r -> mxT[k*16+p] (k = channel) ----
        #pragma unroll
        for (int i = 0; i < 2; i++) {
            const int id = t + 512 * i;     // 0..1023 == c*16+p
            float m0 = pm[id];
            m0 = fmaxf(m0, pm[1040 + id]);
            m0 = fmaxf(m0, pm[2080 + id]);
            m0 = fmaxf(m0, pm[3120 + id]);
            mxT[id] = m0;
        }
        __syncthreads();

        // ---- matvec on first 8 warps: m[c][p] = sigm(w[c].mx[:,p] + b[c]) ----
        if (t < 256) {
            const int c  = t >> 2;
            const int pq = t & 3;
            float4 acc = make_float4(0.f, 0.f, 0.f, 0.f);
            #pragma unroll
            for (int kc = 0; kc < 16; kc++) {
                const float4 w4 = *(const float4*)(wS + c * 68 + kc * 4);
                const float4 m0 = *(const float4*)(mxT + (kc * 4 + 0) * 16 + pq * 4);
                const float4 m1 = *(const float4*)(mxT + (kc * 4 + 1) * 16 + pq * 4);
                const float4 m2 = *(const float4*)(mxT + (kc * 4 + 2) * 16 + pq * 4);
                const float4 m3 = *(const float4*)(mxT + (kc * 4 + 3) * 16 + pq * 4);
                acc.x += w4.x * m0.x + w4.y * m1.x + w4.z * m2.x + w4.w * m3.x;
                acc.y += w4.x * m0.y + w4.y * m1.y + w4.z * m2.y + w4.w * m3.y;
                acc.z += w4.x * m0.z + w4.y * m1.z + w4.z * m2.z + w4.w * m3.z;
                acc.w += w4.x * m0.w + w4.y * m1.w + w4.z * m2.w + w4.w * m3.w;
            }
            const float bc = fcbS[c];
            float4 mres;
            mres.x = sigm(acc.x + bc);
            mres.y = sigm(acc.y + bc);
            mres.z = sigm(acc.z + bc);
            mres.w = sigm(acc.w + bc);
            *(float4*)(msm + c * 16 + pq * 4) = mres;
        }
        __syncthreads();

        // ---- apply channel attention; per-(p,px) partials over 8 channels ----
        float4 ps  = make_float4(0.f, 0.f, 0.f, 0.f);
        float4 pmx = make_float4(-3.4e38f, -3.4e38f, -3.4e38f, -3.4e38f);
        #pragma unroll
        for (int k = 0; k < 8; k++) {
            const float m = msm[(cb + 8 * k) * 16 + p];
            v[k].x *= m; v[k].y *= m; v[k].z *= m; v[k].w *= m;
            ps.x += v[k].x; ps.y += v[k].y; ps.z += v[k].z; ps.w += v[k].w;
            pmx.x = fmaxf(pmx.x, v[k].x); pmx.y = fmaxf(pmx.y, v[k].y);
            pmx.z = fmaxf(pmx.z, v[k].z); pmx.w = fmaxf(pmx.w, v[k].w);
        }
        float* gsum = uni;                  // [cb][rp][px] 2048 floats
        float* gmax = uni + 2048;
        *(float4*)(gsum + cb * 256 + rp * 4) = ps;
        *(float4*)(gmax + cb * 256 + rp * 4) = pmx;
        __syncthreads();

        // ---- g1 per (patch, pixel): reduce over 8 channel groups ----
        if (t < 256) {
            float s = 0.f, mx = -3.4e38f;
            #pragma unroll
            for (int g = 0; g < 8; g++) {
                s  += gsum[g * 256 + t];
                mx  = fmaxf(mx, gmax[g * 256 + t]);
            }
            g1s[t] = sigm(c1w0 * (s * (1.0f / 64.0f)) + c1w1 * mx + c1b0);
        }
        __syncthreads();

        // ---- apply g1; per-patch partials over this thread's 32 values ----
        const float4 g1v = *(const float4*)(g1s + rp * 4);
        float s2 = 0.f, m2 = -3.4e38f;
        #pragma unroll
        for (int k = 0; k < 8; k++) {
            v[k].x *= g1v.x; v[k].y *= g1v.y; v[k].z *= g1v.z; v[k].w *= g1v.w;
            s2 += v[k].x + v[k].y + v[k].z + v[k].w;
            m2 = fmaxf(m2, fmaxf(fmaxf(v[k].x, v[k].y), fmaxf(v[k].z, v[k].w)));
        }

        // ---- g2 per patch: reduce over 32 threads per patch ----
        float* p2s = uni;                   // [group=t>>4][patch] == index t
        float* p2m = uni + 512;
        p2s[t] = s2;
        p2m[t] = m2;
        __syncthreads();
        if (t < 16) {
            float s = 0.f, mx = -3.4e38f;
            #pragma unroll
            for (int g = 0; g < 32; g++) {
                s += p2s[g * 16 + t];
                mx = fmaxf(mx, p2m[g * 16 + t]);
            }
            g2s[t] = sigm(c2w0 * (s * (1.0f / 1024.0f)) + c2w1 * mx + c2b0);
        }
        __syncthreads();
        const float g2 = g2s[p];

        // ---- apply g2 and store directly to global ----
        {
            const int pwg = tau & 3, ph = (tau >> 2) & 63, b = tau >> 8;
            float* ob = out + (size_t)b * 64 * PLANE;
            const int rowbase = (ph * 4 + r) * W_ + pwg * 64 + p * 4;
            #pragma unroll
            for (int k = 0; k < 8; k++) {
                float4 a = v[k];
                a.x *= g2; a.y *= g2; a.z *= g2; a.w *= g2;
                const int c = cb + 8 * k;
                *(float4*)(ob + (size_t)c * PLANE + rowbase) = a;
            }
        }
        __syncthreads();                    // uni reuse safety for next tile
    }
}

extern "C" void kernel_launch(void* const* d_in, const int* in_sizes, int n_in,
                              void* d_out, int out_size) {
    const float* x    = (const float*)d_in[0];
    const float* fc_w = (const float*)d_in[1];
    const float* fc_b = (const float*)d_in[2];
    const float* c1w  = (const float*)d_in[3];
    const float* c1b  = (const float*)d_in[4];
    const float* c2w  = (const float*)d_in[5];
    const float* c2b  = (const float*)d_in[6];
    float* out = (float*)d_out;

    int dev = 0;
    cudaGetDevice(&dev);
    int sms = 0;
    if (cudaDeviceGetAttribute(&sms, cudaDevAttrMultiProcessorCount, dev) != cudaSuccess || sms <= 0)
        sms = 148;

    static_assert(2 * TILE_FLOATS * sizeof(float) == 131072, "stage size");
    cudaFuncSetAttribute(ciam_persist_kernel,
                         cudaFuncAttributeMaxDynamicSharedMemorySize, 131072);

    ciam_persist_kernel<<<sms, THREADS, 131072>>>(x, fc_w, fc_b, c1w, c1b, c2w, c2b, out);
}

// round 5
// speedup vs baseline: 1.0538x; 1.0538x over previous
#include <cuda_runtime.h>
#include <cuda_pipeline.h>

// Problem constants (fixed by the dataset instance)
#define W_ 256
#define PLANE 65536
#define NT 4096              // tiles: 8 b x 64 ph x 8 pwg; tile = 8 patches (64c x 4r x 32w)
#define THREADS 256
#define TILE_FLOATS 8192     // 32 KB

__device__ __forceinline__ float sigm(float x) {
    return 1.0f / (1.0f + __expf(-x));
}

extern __shared__ float stage[];   // 2 x TILE_FLOATS (64 KB dynamic)

__global__ __launch_bounds__(THREADS, 2)
void ciam_pp_kernel(const float* __restrict__ x,
                    const float* __restrict__ fc_w,
                    const float* __restrict__ fc_b,
                    const float* __restrict__ c1w,
                    const float* __restrict__ c1b,
                    const float* __restrict__ c2w,
                    const float* __restrict__ c2b,
                    float* __restrict__ out)
{
    // ---- static shared (~31 KB) ----
    __shared__ float wS[64 * 68];    // fc_w rows, stride 68
    __shared__ float fcbS[64];
    __shared__ float mxT[512];       // channel maxes [c][p], stride 8
    __shared__ float msm[512];       // channel attention m[c][p], stride 8
    __shared__ float gsum[1024];     // g1 partials [cb][rp*4+px]
    __shared__ float gmax[1024];
    __shared__ float g1s[128];       // g1[(r,p)*4+px]
    __shared__ float p2s[64], p2m[64];
    __shared__ float g2s[8];

    const int t  = threadIdx.x;
    const int p  = t & 7;            // patch (within 8-patch group)
    const int r  = (t >> 3) & 3;     // row within patch
    const int cb = t >> 5;           // channel base (c = cb + 8k); == warp id
    const int rp = t & 31;           // (r, p)

    const float c1w0 = __ldg(c1w), c1w1 = __ldg(c1w + 1), c1b0 = __ldg(c1b);
    const float c2w0 = __ldg(c2w), c2w1 = __ldg(c2w + 1), c2b0 = __ldg(c2b);

    // ---- stage fc_w (stride 68) / fc_b once ----
    #pragma unroll
    for (int i = 0; i < 4; i++) {
        const int j  = t + 256 * i;      // float4 chunk 0..1023
        const int c  = j >> 4;
        const int k4 = j & 15;
        *(float4*)(wS + c * 68 + k4 * 4) = *(const float4*)(fc_w + c * 64 + k4 * 4);
    }
    if (t < 64) fcbS[t] = fc_b[t];

    const int grid = gridDim.x;

    // ---- cp.async tile fetch: 2048 16B chunks, 8 per thread ----
    auto issue = [&](int tile, int bf) {
        const int pwg = tile & 7, ph = (tile >> 3) & 63, bb = tile >> 9;
        const float* src = x + (size_t)bb * 64 * PLANE + (ph * 4) * W_ + pwg * 32;
        float* dst = stage + bf * TILE_FLOATS;
        #pragma unroll
        for (int i = 0; i < 8; i++) {
            const int j   = t + 256 * i;
            const int c   = j >> 5;
            const int rw  = j & 31;
            const int rr  = rw >> 3;
            const int w16 = rw & 7;
            __pipeline_memcpy_async(dst + c * 128 + rr * 32 + w16 * 4,
                                    src + (size_t)c * PLANE + rr * W_ + w16 * 4, 16);
        }
    };

    int tau = blockIdx.x;
    if (tau < NT) issue(tau, 0);
    __pipeline_commit();
    if (tau + grid < NT) issue(tau + grid, 1);
    __pipeline_commit();

    int buf = 0;
    for (; tau < NT; tau += grid, buf ^= 1) {
        __pipeline_wait_prior(1);        // current tile's copy complete
        __syncthreads();                 // visibility of all threads' chunks (+smem reuse fence)

        // ---- read v (8 float4 / thread); channel max via shfl over r ----
        const float4* tb = (const float4*)(stage + buf * TILE_FLOATS);
        float4 v[8];
        #pragma unroll
        for (int k = 0; k < 8; k++)
            v[k] = tb[(cb + 8 * k) * 32 + r * 8 + p];
        #pragma unroll
        for (int k = 0; k < 8; k++) {
            float4 a = v[k];
            float rm = fmaxf(fmaxf(a.x, a.y), fmaxf(a.z, a.w));
            rm = fmaxf(rm, __shfl_xor_sync(0xffffffffu, rm, 8));
            rm = fmaxf(rm, __shfl_xor_sync(0xffffffffu, rm, 16));
            if (r == 0) mxT[(cb + 8 * k) * 8 + p] = rm;
        }
        __syncthreads();

        // buffer 'buf' is free now (v in regs) -> prefetch tile tau+2*grid into it
        if (tau + 2 * grid < NT) issue(tau + 2 * grid, buf);
        __pipeline_commit();             // exactly one commit per iteration

        // ---- matvec: m[c][p] = sigm(w[c].mx[:,p] + b[c]); 2 outputs/thread ----
        {
            const int c  = t >> 2;
            const int p0 = (t & 3) * 2;
            float a0 = 0.f, a1 = 0.f;
            #pragma unroll
            for (int kc = 0; kc < 16; kc++) {
                const float4 w4 = *(const float4*)(wS + c * 68 + kc * 4);
                const float2 m0 = *(const float2*)(mxT + (kc * 4 + 0) * 8 + p0);
                const float2 m1 = *(const float2*)(mxT + (kc * 4 + 1) * 8 + p0);
                const float2 m2 = *(const float2*)(mxT + (kc * 4 + 2) * 8 + p0);
                const float2 m3 = *(const float2*)(mxT + (kc * 4 + 3) * 8 + p0);
                a0 += w4.x * m0.x + w4.y * m1.x + w4.z * m2.x + w4.w * m3.x;
                a1 += w4.x * m0.y + w4.y * m1.y + w4.z * m2.y + w4.w * m3.y;
            }
            const float bc = fcbS[c];
            msm[c * 8 + p0]     = sigm(a0 + bc);
            msm[c * 8 + p0 + 1] = sigm(a1 + bc);
        }
        __syncthreads();

        // ---- apply m; g1 partials over this thread's 8 channels ----
        float4 ps  = make_float4(0.f, 0.f, 0.f, 0.f);
        float4 pmx = make_float4(-3.4e38f, -3.4e38f, -3.4e38f, -3.4e38f);
        #pragma unroll
        for (int k = 0; k < 8; k++) {
            const float m = msm[(cb + 8 * k) * 8 + p];
            v[k].x *= m; v[k].y *= m; v[k].z *= m; v[k].w *= m;
            ps.x += v[k].x; ps.y += v[k].y; ps.z += v[k].z; ps.w += v[k].w;
            pmx.x = fmaxf(pmx.x, v[k].x); pmx.y = fmaxf(pmx.y, v[k].y);
            pmx.z = fmaxf(pmx.z, v[k].z); pmx.w = fmaxf(pmx.w, v[k].w);
        }
        *(float4*)(gsum + cb * 128 + rp * 4) = ps;
        *(float4*)(gmax + cb * 128 + rp * 4) = pmx;
        __syncthreads();

        // ---- g1 per (patch, pixel): reduce over 8 channel groups ----
        if (t < 128) {
            float s = 0.f, mx = -3.4e38f;
            #pragma unroll
            for (int g = 0; g < 8; g++) {
                s  += gsum[g * 128 + t];
                mx  = fmaxf(mx, gmax[g * 128 + t]);
            }
            g1s[t] = sigm(c1w0 * (s * (1.0f / 64.0f)) + c1w1 * mx + c1b0);
        }
        __syncthreads();

        // ---- apply g1; g2 partials; shfl-reduce over r ----
        const float4 g1v = *(const float4*)(g1s + rp * 4);
        float s2 = 0.f, m2 = -3.4e38f;
        #pragma unroll
        for (int k = 0; k < 8; k++) {
            v[k].x *= g1v.x; v[k].y *= g1v.y; v[k].z *= g1v.z; v[k].w *= g1v.w;
            s2 += v[k].x + v[k].y + v[k].z + v[k].w;
            m2 = fmaxf(m2, fmaxf(fmaxf(v[k].x, v[k].y), fmaxf(v[k].z, v[k].w)));
        }
        s2 += __shfl_xor_sync(0xffffffffu, s2, 8);
        m2 = fmaxf(m2, __shfl_xor_sync(0xffffffffu, m2, 8));
        s2 += __shfl_xor_sync(0xffffffffu, s2, 16);
        m2 = fmaxf(m2, __shfl_xor_sync(0xffffffffu, m2, 16));
        if (rp < 8) { p2s[cb * 8 + p] = s2; p2m[cb * 8 + p] = m2; }
        __syncthreads();
        if (t < 8) {
            float s = 0.f, mx = -3.4e38f;
            #pragma unroll
            for (int g = 0; g < 8; g++) {
                s += p2s[g * 8 + t];
                mx = fmaxf(mx, p2m[g * 8 + t]);
            }
            g2s[t] = sigm(c2w0 * (s * (1.0f / 1024.0f)) + c2w1 * mx + c2b0);
        }
        __syncthreads();
        const float g2 = g2s[p];

        // ---- apply g2 and store ----
        {
            const int pwg = tau & 7, ph = (tau >> 3) & 63, bb = tau >> 9;
            float* ob = out + (size_t)bb * 64 * PLANE
                            + (size_t)((ph * 4 + r) * W_ + pwg * 32 + p * 4);
            #pragma unroll
            for (int k = 0; k < 8; k++) {
                float4 a = v[k];
                a.x *= g2; a.y *= g2; a.z *= g2; a.w *= g2;
                *(float4*)(ob + (size_t)(cb + 8 * k) * PLANE) = a;
            }
        }
        // no tail sync needed: next iteration's first smem write (mxT) is
        // preceded by the top-of-loop __syncthreads.
    }
}

extern "C" void kernel_launch(void* const* d_in, const int* in_sizes, int n_in,
                              void* d_out, int out_size) {
    const float* x    = (const float*)d_in[0];
    const float* fc_w = (const float*)d_in[1];
    const float* fc_b = (const float*)d_in[2];
    const float* c1w  = (const float*)d_in[3];
    const float* c1b  = (const float*)d_in[4];
    const float* c2w  = (const float*)d_in[5];
    const float* c2b  = (const float*)d_in[6];
    float* out = (float*)d_out;

    int dev = 0;
    cudaGetDevice(&dev);
    int sms = 0;
    if (cudaDeviceGetAttribute(&sms, cudaDevAttrMultiProcessorCount, dev) != cudaSuccess || sms <= 0)
        sms = 148;

    const int dyn = 2 * TILE_FLOATS * sizeof(float);   // 64 KB
    cudaFuncSetAttribute(ciam_pp_kernel,
                         cudaFuncAttributeMaxDynamicSharedMemorySize, dyn);

    int grid = 2 * sms;
    if (grid > NT) grid = NT;
    ciam_pp_kernel<<<grid, THREADS, dyn>>>(x, fc_w, fc_b, c1w, c1b, c2w, c2b, out);
}

// round 6
// speedup vs baseline: 1.1935x; 1.1325x over previous
#include <cuda_runtime.h>

// Problem constants (fixed by the dataset instance)
#define W_ 256
#define PLANE 65536
#define THREADS 512
// tile = 16 patches (64c x 4r x 64w) -> 2048 tiles, one block each

__device__ __forceinline__ float sigm(float x) {
    return 1.0f / (1.0f + __expf(-x));
}

__global__ __launch_bounds__(THREADS, 2)
void ciam_wide_kernel(const float* __restrict__ x,
                      const float* __restrict__ fc_w,
                      const float* __restrict__ fc_b,
                      const float* __restrict__ c1w,
                      const float* __restrict__ c1b,
                      const float* __restrict__ c2w,
                      const float* __restrict__ c2b,
                      float* __restrict__ out)
{
    // ---- block / thread decomposition ----
    const int blk = blockIdx.x;          // 0..2047
    const int pwg = blk & 3;             // 16-patch group along W
    const int ph  = (blk >> 2) & 63;     // patch row
    const int b   = blk >> 8;            // batch

    const int t  = threadIdx.x;
    const int p  = t & 15;               // patch
    const int r  = (t >> 4) & 3;         // row within patch
    const int cb = t >> 6;               // channel base 0..7 (c = cb + 8k, k<8)
    const int rp = t & 63;               // (r, patch)

    // ---- shared memory (~43 KB) ----
    __shared__ float wS[64 * 68];        // fc_w rows, stride 68
    __shared__ float fcbS[64];
    __shared__ float mxT[1024];          // channel maxes, k-major [k][p] (k=c)
    __shared__ float msm[1024];          // channel attention m[c][p]
    __shared__ float g1s[256];           // g1[(r,p)*4 + px]
    __shared__ float p2s[256], p2m[256]; // g2 partials [warp][p]
    __shared__ float g2s[16];
    __shared__ float uni[4160];          // pm[4][1040] / gsum+gmax[2048+2048]

    // ---- scalar weights ----
    const float c1w0 = __ldg(c1w), c1w1 = __ldg(c1w + 1), c1b0 = __ldg(c1b);
    const float c2w0 = __ldg(c2w), c2w1 = __ldg(c2w + 1), c2b0 = __ldg(c2b);

    // ---- load tile into registers (8 x float4 / thread, coalesced) ----
    const size_t plane = PLANE;
    const float* xb = x + (size_t)b * 64 * plane;
    float* ob = out + (size_t)b * 64 * plane;
    const int rowbase = (ph * 4 + r) * W_ + pwg * 64 + p * 4;

    float4 v[8];
    #pragma unroll
    for (int k = 0; k < 8; k++)
        v[k] = *(const float4*)(xb + (size_t)(cb + 8 * k) * plane + rowbase);

    // ---- stage fc_w (stride 68) / fc_b ----
    #pragma unroll
    for (int i = 0; i < 2; i++) {
        const int j  = t + 512 * i;      // float4 chunk 0..1023
        const int c  = j >> 4;
        const int k4 = j & 15;
        *(float4*)(wS + c * 68 + k4 * 4) = *(const float4*)(fc_w + c * 64 + k4 * 4);
    }
    if (t < 64) fcbS[t] = fc_b[t];

    // ---- per-(c,r,p) row max -> pm (row stride 1040, conflict-free) ----
    float* pm = uni;                     // [r][c*16+p]
    #pragma unroll
    for (int k = 0; k < 8; k++) {
        float4 a = v[k];
        pm[r * 1040 + (cb + 8 * k) * 16 + p] =
            fmaxf(fmaxf(a.x, a.y), fmaxf(a.z, a.w));
    }
    __syncthreads();

    // ---- reduce over r -> mxT[c*16+p] ----
    #pragma unroll
    for (int i = 0; i < 2; i++) {
        const int id = t + 512 * i;      // 0..1023 == c*16 + p
        float m0 = pm[id];
        m0 = fmaxf(m0, pm[1040 + id]);
        m0 = fmaxf(m0, pm[2080 + id]);
        m0 = fmaxf(m0, pm[3120 + id]);
        mxT[id] = m0;
    }
    __syncthreads();

    // ---- matvec: m[c][p] = sigm(w[c].mx[:,p] + b[c]); 2 outputs/thread ----
    {
        const int c  = t >> 3;           // 0..63
        const int p0 = (t & 7) * 2;      // 0,2,..,14
        float a0 = 0.f, a1 = 0.f;
        #pragma unroll
        for (int kc = 0; kc < 16; kc++) {
            const float4 w4 = *(const float4*)(wS + c * 68 + kc * 4);
            const float2 m0 = *(const float2*)(mxT + (kc * 4 + 0) * 16 + p0);
            const float2 m1 = *(const float2*)(mxT + (kc * 4 + 1) * 16 + p0);
            const float2 m2 = *(const float2*)(mxT + (kc * 4 + 2) * 16 + p0);
            const float2 m3 = *(const float2*)(mxT + (kc * 4 + 3) * 16 + p0);
            a0 += w4.x * m0.x + w4.y * m1.x + w4.z * m2.x + w4.w * m3.x;
            a1 += w4.x * m0.y + w4.y * m1.y + w4.z * m2.y + w4.w * m3.y;
        }
        const float bc = fcbS[c];
        *(float2*)(msm + c * 16 + p0) = make_float2(sigm(a0 + bc), sigm(a1 + bc));
    }
    __syncthreads();

    // ---- apply channel attention; g1 partials over this thread's 8 channels ----
    float4 ps  = make_float4(0.f, 0.f, 0.f, 0.f);
    float4 pmx = make_float4(-3.4e38f, -3.4e38f, -3.4e38f, -3.4e38f);
    #pragma unroll
    for (int k = 0; k < 8; k++) {
        const float m = msm[(cb + 8 * k) * 16 + p];
        v[k].x *= m; v[k].y *= m; v[k].z *= m; v[k].w *= m;
        ps.x += v[k].x; ps.y += v[k].y; ps.z += v[k].z; ps.w += v[k].w;
        pmx.x = fmaxf(pmx.x, v[k].x); pmx.y = fmaxf(pmx.y, v[k].y);
        pmx.z = fmaxf(pmx.z, v[k].z); pmx.w = fmaxf(pmx.w, v[k].w);
    }
    float* gsum = uni;                   // [cb][rp*4+px] : 2048 floats
    float* gmax = uni + 2048;
    *(float4*)(gsum + cb * 256 + rp * 4) = ps;
    *(float4*)(gmax + cb * 256 + rp * 4) = pmx;
    __syncthreads();

    // ---- g1 per (patch, pixel): reduce over the 8 channel-base groups ----
    if (t < 256) {
        float s = 0.f, mx = -3.4e38f;
        #pragma unroll
        for (int g = 0; g < 8; g++) {
            s  += gsum[g * 256 + t];
            mx  = fmaxf(mx, gmax[g * 256 + t]);
        }
        g1s[t] = sigm(c1w0 * (s * (1.0f / 64.0f)) + c1w1 * mx + c1b0);
    }
    __syncthreads();

    // ---- apply g1; g2 partials over this thread's 32 values ----
    const float4 g1v = *(const float4*)(g1s + rp * 4);
    float s2 = 0.f, m2 = -3.4e38f;
    #pragma unroll
    for (int k = 0; k < 8; k++) {
        v[k].x *= g1v.x; v[k].y *= g1v.y; v[k].z *= g1v.z; v[k].w *= g1v.w;
        s2 += v[k].x + v[k].y + v[k].z + v[k].w;
        m2 = fmaxf(m2, fmaxf(fmaxf(v[k].x, v[k].y), fmaxf(v[k].z, v[k].w)));
    }
    // combine the two r-values within each warp (lanes differ by bit 4)
    s2 += __shfl_xor_sync(0xffffffffu, s2, 16);
    m2 = fmaxf(m2, __shfl_xor_sync(0xffffffffu, m2, 16));
    if ((t & 16) == 0)
        { p2s[(t >> 5) * 16 + p] = s2; p2m[(t >> 5) * 16 + p] = m2; }
    __syncthreads();
    if (t < 16) {
        float s = 0.f, mx = -3.4e38f;
        #pragma unroll
        for (int g = 0; g < 16; g++) {
            s += p2s[g * 16 + t];
            mx = fmaxf(mx, p2m[g * 16 + t]);
        }
        g2s[t] = sigm(c2w0 * (s * (1.0f / 1024.0f)) + c2w1 * mx + c2b0);
    }
    __syncthreads();
    const float g2 = g2s[p];

    // ---- apply g2 and store (same coalesced pattern as load) ----
    #pragma unroll
    for (int k = 0; k < 8; k++) {
        float4 a = v[k];
        a.x *= g2; a.y *= g2; a.z *= g2; a.w *= g2;
        *(float4*)(ob + (size_t)(cb + 8 * k) * plane + rowbase) = a;
    }
}

extern "C" void kernel_launch(void* const* d_in, const int* in_sizes, int n_in,
                              void* d_out, int out_size) {
    const float* x    = (const float*)d_in[0];
    const float* fc_w = (const float*)d_in[1];
    const float* fc_b = (const float*)d_in[2];
    const float* c1w  = (const float*)d_in[3];
    const float* c1b  = (const float*)d_in[4];
    const float* c2w  = (const float*)d_in[5];
    const float* c2b  = (const float*)d_in[6];
    float* out = (float*)d_out;

    // 2048 blocks: 8 batches x 64 patch-rows x 4 groups of 16 patches
    ciam_wide_kernel<<<2048, THREADS>>>(x, fc_w, fc_b, c1w, c1b, c2w, c2b, out);
}